// round 3
// baseline (speedup 1.0000x reference)
#include <cuda_runtime.h>

#define N_NODES 100000
#define N_EDGES 1600000
#define IN_CH   768
#define HID_CH  256
#define OUT_CH  2

#define SCAN_B 1024
#define N_SCAN_BLKS ((N_NODES + SCAN_B - 1) / SCAN_B)   // 98

// ---- scratch (device globals; allocation is forbidden) ----
__device__ __align__(16) float g_xw[(size_t)N_NODES * HID_CH]; // x @ W1
__device__ float g_deg [N_NODES];
__device__ float g_dinv[N_NODES];
__device__ __align__(8) float g_hw[(size_t)N_NODES * OUT_CH];  // relu(h) @ W2
__device__ int   g_src[N_EDGES];
__device__ int   g_dst[N_EDGES];
__device__ int   g_cnt[N_NODES];        // in-degree (edge count) per dst
__device__ int   g_off[N_NODES];        // exclusive CSR offsets
__device__ int   g_cursor[N_NODES];
__device__ int   g_bsum[N_SCAN_BLKS];
__device__ int   g_csr_src[N_EDGES];
__device__ float g_csr_nrm[N_EDGES];
__device__ int   g_is64;

// ---- detect whether edge_index is int64 or int32 ----
__global__ void k_detect(const unsigned long long* __restrict__ ei) {
    if (threadIdx.x == 0 && blockIdx.x == 0) {
        int is64 = 1;
        for (int i = 0; i < 1024; i++) {
            if ((ei[i] >> 32) != 0ull) { is64 = 0; break; }
        }
        g_is64 = is64;
    }
}

// ---- init: weighted degree starts at 1.0 (self loop), counts at 0 ----
__global__ void k_init() {
    int i = blockIdx.x * blockDim.x + threadIdx.x;
    if (i < N_NODES) { g_deg[i] = 1.0f; g_cnt[i] = 0; }
}

// ---- pass 1 over edges: decode indices, weighted degree, count ----
__global__ void k_prep(const void* __restrict__ ei_raw, const float* __restrict__ ew) {
    int e = blockIdx.x * blockDim.x + threadIdx.x;
    if (e >= N_EDGES) return;
    int s, d;
    if (g_is64) {
        const long long* ei = (const long long*)ei_raw;
        s = (int)ei[e];
        d = (int)ei[N_EDGES + e];
    } else {
        const int* ei = (const int*)ei_raw;
        s = ei[e];
        d = ei[N_EDGES + e];
    }
    if ((unsigned)s >= N_NODES || (unsigned)d >= N_NODES) { // defensive: never crash
        g_src[e] = 0; g_dst[e] = 0;
        return;
    }
    g_src[e] = s;
    g_dst[e] = d;
    atomicAdd(&g_deg[d], ew[e]);
    atomicAdd(&g_cnt[d], 1);
}

__global__ void k_dinv() {
    int i = blockIdx.x * blockDim.x + threadIdx.x;
    if (i < N_NODES) {
        float dg = g_deg[i];
        g_dinv[i] = dg > 0.f ? rsqrtf(dg) : 0.f;
    }
}

// ---- two-level exclusive scan of g_cnt -> g_off ----
__global__ void k_scan1() {
    __shared__ int s[SCAN_B];
    int tid = threadIdx.x;
    int i = blockIdx.x * SCAN_B + tid;
    int v = (i < N_NODES) ? g_cnt[i] : 0;
    s[tid] = v;
    __syncthreads();
    #pragma unroll
    for (int d = 1; d < SCAN_B; d <<= 1) {
        int t = (tid >= d) ? s[tid - d] : 0;
        __syncthreads();
        s[tid] += t;
        __syncthreads();
    }
    if (i < N_NODES) g_off[i] = s[tid] - v;          // exclusive within block
    if (tid == SCAN_B - 1) g_bsum[blockIdx.x] = s[tid];
}

__global__ void k_scan2() {
    __shared__ int s[128];
    int tid = threadIdx.x;
    int v = (tid < N_SCAN_BLKS) ? g_bsum[tid] : 0;
    s[tid] = v;
    __syncthreads();
    #pragma unroll
    for (int d = 1; d < 128; d <<= 1) {
        int t = (tid >= d) ? s[tid - d] : 0;
        __syncthreads();
        s[tid] += t;
        __syncthreads();
    }
    if (tid < N_SCAN_BLKS) g_bsum[tid] = s[tid] - v; // exclusive block sums
}

__global__ void k_scan3() {
    int i = blockIdx.x * blockDim.x + threadIdx.x;
    if (i < N_NODES) {
        int o = g_off[i] + g_bsum[i / SCAN_B];
        g_off[i] = o;
        g_cursor[i] = o;
    }
}

// ---- pass 2 over edges: scatter into CSR buckets with precomputed norm ----
__global__ void k_scatter(const float* __restrict__ ew) {
    int e = blockIdx.x * blockDim.x + threadIdx.x;
    if (e >= N_EDGES) return;
    int s = g_src[e];
    int d = g_dst[e];
    int pos = atomicAdd(&g_cursor[d], 1);
    if ((unsigned)pos >= N_EDGES) return;  // defensive
    g_csr_src[pos] = s;
    g_csr_nrm[pos] = g_dinv[s] * ew[e] * g_dinv[d];
}

// ---- GEMM1: g_xw = x @ W1  (M=100000, K=768, N=256), 128x128x16 tiles ----
__global__ __launch_bounds__(256, 2)
void k_gemm1(const float* __restrict__ A, const float* __restrict__ B) {
    __shared__ float As[16][128];
    __shared__ float Bs[16][128];
    const int tid = threadIdx.x;
    const int m0 = blockIdx.x * 128;
    const int n0 = blockIdx.y * 128;
    const int tx = tid & 15;
    const int ty = tid >> 4;

    float acc[8][8];
    #pragma unroll
    for (int i = 0; i < 8; i++)
        #pragma unroll
        for (int j = 0; j < 8; j++) acc[i][j] = 0.f;

    for (int k0 = 0; k0 < IN_CH; k0 += 16) {
        #pragma unroll
        for (int i = 0; i < 2; i++) {
            int idx = tid + i * 256;
            int row = idx >> 2, c4 = idx & 3;
            int gm = m0 + row;
            float4 v = make_float4(0.f, 0.f, 0.f, 0.f);
            if (gm < N_NODES)
                v = *(const float4*)(A + (size_t)gm * IN_CH + k0 + c4 * 4);
            As[c4 * 4 + 0][row] = v.x;
            As[c4 * 4 + 1][row] = v.y;
            As[c4 * 4 + 2][row] = v.z;
            As[c4 * 4 + 3][row] = v.w;
        }
        #pragma unroll
        for (int i = 0; i < 2; i++) {
            int idx = tid + i * 256;
            int row = idx >> 5, c4 = idx & 31;
            *(float4*)&Bs[row][c4 * 4] =
                *(const float4*)(B + (size_t)(k0 + row) * HID_CH + n0 + c4 * 4);
        }
        __syncthreads();

        #pragma unroll
        for (int k = 0; k < 16; k++) {
            float4 a0 = *(const float4*)&As[k][ty * 8];
            float4 a1 = *(const float4*)&As[k][ty * 8 + 4];
            float4 b0 = *(const float4*)&Bs[k][tx * 8];
            float4 b1 = *(const float4*)&Bs[k][tx * 8 + 4];
            float a[8] = {a0.x, a0.y, a0.z, a0.w, a1.x, a1.y, a1.z, a1.w};
            float b[8] = {b0.x, b0.y, b0.z, b0.w, b1.x, b1.y, b1.z, b1.w};
            #pragma unroll
            for (int i = 0; i < 8; i++)
                #pragma unroll
                for (int j = 0; j < 8; j++)
                    acc[i][j] += a[i] * b[j];
        }
        __syncthreads();
    }

    #pragma unroll
    for (int i = 0; i < 8; i++) {
        int gm = m0 + ty * 8 + i;
        if (gm >= N_NODES) continue;
        float* crow = g_xw + (size_t)gm * HID_CH + n0 + tx * 8;
        *(float4*)(crow)     = make_float4(acc[i][0], acc[i][1], acc[i][2], acc[i][3]);
        *(float4*)(crow + 4) = make_float4(acc[i][4], acc[i][5], acc[i][6], acc[i][7]);
    }
}

// ---- fused layer-1 aggregation + bias + ReLU + GEMM2 (256 -> 2) ----
// One warp per destination node. Each lane owns 8 channels in registers.
__global__ __launch_bounds__(256)
void k_agg_fused(const float* __restrict__ b1, const float* __restrict__ W2) {
    __shared__ float sW2[HID_CH * OUT_CH];
    __shared__ float sb1[HID_CH];
    int tid = threadIdx.x;
    sW2[tid] = W2[tid];
    sW2[tid + 256] = W2[tid + 256];
    sb1[tid] = b1[tid];
    __syncthreads();

    int node = (blockIdx.x * blockDim.x + tid) >> 5;
    int lane = tid & 31;
    if (node >= N_NODES) return;

    // self-loop term: dinv[n]^2 * xw[n]
    float di = g_dinv[node];
    float self = di * di;
    const float4* nrow = (const float4*)(g_xw + (size_t)node * HID_CH) + lane * 2;
    float4 v0 = nrow[0], v1 = nrow[1];
    float4 acc0 = make_float4(self * v0.x, self * v0.y, self * v0.z, self * v0.w);
    float4 acc1 = make_float4(self * v1.x, self * v1.y, self * v1.z, self * v1.w);

    int begin = g_off[node];
    int end = begin + g_cnt[node];
    for (int j0 = begin; j0 < end; j0 += 32) {
        int m = end - j0; if (m > 32) m = 32;
        int   s_l = (lane < m) ? g_csr_src[j0 + lane] : 0;
        float w_l = (lane < m) ? g_csr_nrm[j0 + lane] : 0.f;
        for (int t = 0; t < m; t++) {
            int   s = __shfl_sync(0xffffffffu, s_l, t);
            float w = __shfl_sync(0xffffffffu, w_l, t);
            const float4* r = (const float4*)(g_xw + (size_t)s * HID_CH) + lane * 2;
            float4 u0 = __ldg(r);
            float4 u1 = __ldg(r + 1);
            acc0.x += w * u0.x; acc0.y += w * u0.y; acc0.z += w * u0.z; acc0.w += w * u0.w;
            acc1.x += w * u1.x; acc1.y += w * u1.y; acc1.z += w * u1.z; acc1.w += w * u1.w;
        }
    }

    // bias + relu + 256->2 dot
    int c = lane * 8;
    float h[8];
    h[0] = fmaxf(acc0.x + sb1[c + 0], 0.f);
    h[1] = fmaxf(acc0.y + sb1[c + 1], 0.f);
    h[2] = fmaxf(acc0.z + sb1[c + 2], 0.f);
    h[3] = fmaxf(acc0.w + sb1[c + 3], 0.f);
    h[4] = fmaxf(acc1.x + sb1[c + 4], 0.f);
    h[5] = fmaxf(acc1.y + sb1[c + 5], 0.f);
    h[6] = fmaxf(acc1.z + sb1[c + 6], 0.f);
    h[7] = fmaxf(acc1.w + sb1[c + 7], 0.f);
    float a0 = 0.f, a1 = 0.f;
    #pragma unroll
    for (int i = 0; i < 8; i++) {
        a0 += h[i] * sW2[(c + i) * 2];
        a1 += h[i] * sW2[(c + i) * 2 + 1];
    }
    #pragma unroll
    for (int off = 16; off > 0; off >>= 1) {
        a0 += __shfl_down_sync(0xffffffffu, a0, off);
        a1 += __shfl_down_sync(0xffffffffu, a1, off);
    }
    if (lane == 0) {
        g_hw[node * 2]     = a0;
        g_hw[node * 2 + 1] = a1;
    }
}

// ---- layer-2 aggregation via CSR: one thread per node, no atomics ----
__global__ void k_out2(const float* __restrict__ b2, float* __restrict__ out) {
    int n = blockIdx.x * blockDim.x + threadIdx.x;
    if (n >= N_NODES) return;
    float di = g_dinv[n];
    float self = di * di;
    float a0 = g_hw[2 * n]     * self;
    float a1 = g_hw[2 * n + 1] * self;
    int begin = g_off[n];
    int end = begin + g_cnt[n];
    for (int j = begin; j < end; j++) {
        int   s = g_csr_src[j];
        float w = g_csr_nrm[j];
        a0 += w * g_hw[2 * s];
        a1 += w * g_hw[2 * s + 1];
    }
    out[2 * n]     = a0 + b2[0];
    out[2 * n + 1] = a1 + b2[1];
}

extern "C" void kernel_launch(void* const* d_in, const int* in_sizes, int n_in,
                              void* d_out, int out_size) {
    const float* x  = (const float*)d_in[0];
    const void*  ei = d_in[1];
    const float* ew = (const float*)d_in[2];
    const float* W1 = (const float*)d_in[3];
    const float* b1 = (const float*)d_in[4];
    const float* W2 = (const float*)d_in[5];
    const float* b2 = (const float*)d_in[6];
    float* out = (float*)d_out;

    const int NODE_BLKS = (N_NODES + 255) / 256;
    const int EDGE_BLKS = (N_EDGES + 255) / 256;

    k_detect<<<1, 32>>>((const unsigned long long*)ei);
    k_init<<<NODE_BLKS, 256>>>();
    k_prep<<<EDGE_BLKS, 256>>>(ei, ew);
    k_dinv<<<NODE_BLKS, 256>>>();
    k_scan1<<<N_SCAN_BLKS, SCAN_B>>>();
    k_scan2<<<1, 128>>>();
    k_scan3<<<NODE_BLKS, 256>>>();
    k_scatter<<<EDGE_BLKS, 256>>>(ew);

    dim3 g1((N_NODES + 127) / 128, HID_CH / 128);
    k_gemm1<<<g1, 256>>>(x, W1);

    // one warp per node
    k_agg_fused<<<(N_NODES * 32 + 255) / 256, 256>>>(b1, W2);

    k_out2<<<NODE_BLKS, 256>>>(b2, out);
}

// round 4
// speedup vs baseline: 1.6127x; 1.6127x over previous
#include <cuda_runtime.h>
#include <cuda_bf16.h>
#include <cstdint>

#define N_NODES 100000
#define N_EDGES 1600000
#define IN_CH   768
#define HID_CH  256
#define OUT_CH  2

#define SCAN_B 1024
#define N_SCAN_BLKS ((N_NODES + SCAN_B - 1) / SCAN_B)   // 98

// ---- scratch (device globals; allocation is forbidden) ----
__device__ __align__(16) float g_xw[(size_t)N_NODES * HID_CH]; // x @ W1
__device__ float g_deg [N_NODES];
__device__ float g_dinv[N_NODES];
__device__ __align__(8) float g_hw[(size_t)N_NODES * OUT_CH];  // relu(h) @ W2
__device__ int   g_src[N_EDGES];
__device__ int   g_dst[N_EDGES];
__device__ int   g_cnt[N_NODES];
__device__ int   g_off[N_NODES];
__device__ int   g_cursor[N_NODES];
__device__ int   g_bsum[N_SCAN_BLKS];
__device__ int   g_csr_src[N_EDGES];
__device__ float g_csr_nrm[N_EDGES];
__device__ int   g_is64;

// ---- detect whether edge_index is int64 or int32 ----
__global__ void k_detect(const unsigned long long* __restrict__ ei) {
    if (threadIdx.x == 0 && blockIdx.x == 0) {
        int is64 = 1;
        for (int i = 0; i < 1024; i++) {
            if ((ei[i] >> 32) != 0ull) { is64 = 0; break; }
        }
        g_is64 = is64;
    }
}

__global__ void k_init() {
    int i = blockIdx.x * blockDim.x + threadIdx.x;
    if (i < N_NODES) { g_deg[i] = 1.0f; g_cnt[i] = 0; }
}

__global__ void k_prep(const void* __restrict__ ei_raw, const float* __restrict__ ew) {
    int e = blockIdx.x * blockDim.x + threadIdx.x;
    if (e >= N_EDGES) return;
    int s, d;
    if (g_is64) {
        const long long* ei = (const long long*)ei_raw;
        s = (int)ei[e];
        d = (int)ei[N_EDGES + e];
    } else {
        const int* ei = (const int*)ei_raw;
        s = ei[e];
        d = ei[N_EDGES + e];
    }
    if ((unsigned)s >= N_NODES || (unsigned)d >= N_NODES) {
        g_src[e] = 0; g_dst[e] = 0;
        return;
    }
    g_src[e] = s;
    g_dst[e] = d;
    atomicAdd(&g_deg[d], ew[e]);
    atomicAdd(&g_cnt[d], 1);
}

__global__ void k_dinv() {
    int i = blockIdx.x * blockDim.x + threadIdx.x;
    if (i < N_NODES) {
        float dg = g_deg[i];
        g_dinv[i] = dg > 0.f ? rsqrtf(dg) : 0.f;
    }
}

// ---- two-level exclusive scan ----
__global__ void k_scan1() {
    __shared__ int s[SCAN_B];
    int tid = threadIdx.x;
    int i = blockIdx.x * SCAN_B + tid;
    int v = (i < N_NODES) ? g_cnt[i] : 0;
    s[tid] = v;
    __syncthreads();
    #pragma unroll
    for (int d = 1; d < SCAN_B; d <<= 1) {
        int t = (tid >= d) ? s[tid - d] : 0;
        __syncthreads();
        s[tid] += t;
        __syncthreads();
    }
    if (i < N_NODES) g_off[i] = s[tid] - v;
    if (tid == SCAN_B - 1) g_bsum[blockIdx.x] = s[tid];
}

__global__ void k_scan2() {
    __shared__ int s[128];
    int tid = threadIdx.x;
    int v = (tid < N_SCAN_BLKS) ? g_bsum[tid] : 0;
    s[tid] = v;
    __syncthreads();
    #pragma unroll
    for (int d = 1; d < 128; d <<= 1) {
        int t = (tid >= d) ? s[tid - d] : 0;
        __syncthreads();
        s[tid] += t;
        __syncthreads();
    }
    if (tid < N_SCAN_BLKS) g_bsum[tid] = s[tid] - v;
}

__global__ void k_scan3() {
    int i = blockIdx.x * blockDim.x + threadIdx.x;
    if (i < N_NODES) {
        int o = g_off[i] + g_bsum[i / SCAN_B];
        g_off[i] = o;
        g_cursor[i] = o;
    }
}

__global__ void k_scatter(const float* __restrict__ ew) {
    int e = blockIdx.x * blockDim.x + threadIdx.x;
    if (e >= N_EDGES) return;
    int s = g_src[e];
    int d = g_dst[e];
    int pos = atomicAdd(&g_cursor[d], 1);
    if ((unsigned)pos >= N_EDGES) return;
    g_csr_src[pos] = s;
    g_csr_nrm[pos] = g_dinv[s] * ew[e] * g_dinv[d];
}

// ================= tensor-core GEMM1 (bf16 split, 3-pass) =================
__device__ __forceinline__ uint32_t smem_u32(const void* p) {
    return (uint32_t)__cvta_generic_to_shared(p);
}
__device__ __forceinline__ void ldsm_x4(uint32_t* r, uint32_t addr) {
    asm volatile("ldmatrix.sync.aligned.m8n8.x4.shared.b16 {%0,%1,%2,%3}, [%4];"
        : "=r"(r[0]), "=r"(r[1]), "=r"(r[2]), "=r"(r[3]) : "r"(addr));
}
__device__ __forceinline__ void ldsm_x2t(uint32_t* r, uint32_t addr) {
    asm volatile("ldmatrix.sync.aligned.m8n8.x2.trans.shared.b16 {%0,%1}, [%2];"
        : "=r"(r[0]), "=r"(r[1]) : "r"(addr));
}
__device__ __forceinline__ void mma_bf16(float* c, const uint32_t* a, const uint32_t* b) {
    asm volatile("mma.sync.aligned.m16n8k16.row.col.f32.bf16.bf16.f32 "
        "{%0,%1,%2,%3}, {%4,%5,%6,%7}, {%8,%9}, {%0,%1,%2,%3};"
        : "+f"(c[0]), "+f"(c[1]), "+f"(c[2]), "+f"(c[3])
        : "r"(a[0]), "r"(a[1]), "r"(a[2]), "r"(a[3]), "r"(b[0]), "r"(b[1]));
}
__device__ __forceinline__ void split_bf16(float v, __nv_bfloat16& h, __nv_bfloat16& l) {
    h = __float2bfloat16(v);
    l = __float2bfloat16(v - __bfloat162float(h));
}

#define BM 128
#define BN 128
#define BK 32
#define A_PITCH 40
#define B_PITCH 136

__global__ __launch_bounds__(256, 1)
void k_gemm1_tc(const float* __restrict__ A, const float* __restrict__ B) {
    __shared__ __align__(16) __nv_bfloat16 Ah[BM][A_PITCH];
    __shared__ __align__(16) __nv_bfloat16 Al[BM][A_PITCH];
    __shared__ __align__(16) __nv_bfloat16 Bh[BK][B_PITCH];
    __shared__ __align__(16) __nv_bfloat16 Bl[BK][B_PITCH];

    const int tid  = threadIdx.x;
    const int lane = tid & 31;
    const int wid  = tid >> 5;
    const int warp_m = wid >> 1;   // 0..3, 32 rows each
    const int warp_n = wid & 1;    // 0..1, 64 cols each
    const int m0 = blockIdx.x * BM;
    const int n0 = blockIdx.y * BN;

    float acc[2][8][4];
    #pragma unroll
    for (int mi = 0; mi < 2; mi++)
        #pragma unroll
        for (int ni = 0; ni < 8; ni++)
            #pragma unroll
            for (int q = 0; q < 4; q++) acc[mi][ni][q] = 0.f;

    for (int k0 = 0; k0 < IN_CH; k0 += BK) {
        // ---- load + split A tile (BM x BK floats) ----
        #pragma unroll
        for (int i = 0; i < 4; i++) {
            int lin = tid + i * 256;           // 0..1023, 8 float4 per row
            int r = lin >> 3, c = (lin & 7) * 4;
            float4 v = make_float4(0.f, 0.f, 0.f, 0.f);
            if (m0 + r < N_NODES)
                v = *(const float4*)(A + (size_t)(m0 + r) * IN_CH + k0 + c);
            __nv_bfloat16 h0, l0, h1, l1, h2, l2, h3, l3;
            split_bf16(v.x, h0, l0); split_bf16(v.y, h1, l1);
            split_bf16(v.z, h2, l2); split_bf16(v.w, h3, l3);
            *(__nv_bfloat162*)&Ah[r][c]     = __nv_bfloat162(h0, h1);
            *(__nv_bfloat162*)&Ah[r][c + 2] = __nv_bfloat162(h2, h3);
            *(__nv_bfloat162*)&Al[r][c]     = __nv_bfloat162(l0, l1);
            *(__nv_bfloat162*)&Al[r][c + 2] = __nv_bfloat162(l2, l3);
        }
        // ---- load + split B tile (BK x BN floats), keep k-major rows ----
        #pragma unroll
        for (int i = 0; i < 4; i++) {
            int lin = tid + i * 256;           // 32 float4 per row
            int r = lin >> 5, c = (lin & 31) * 4;
            float4 v = *(const float4*)(B + (size_t)(k0 + r) * HID_CH + n0 + c);
            __nv_bfloat16 h0, l0, h1, l1, h2, l2, h3, l3;
            split_bf16(v.x, h0, l0); split_bf16(v.y, h1, l1);
            split_bf16(v.z, h2, l2); split_bf16(v.w, h3, l3);
            *(__nv_bfloat162*)&Bh[r][c]     = __nv_bfloat162(h0, h1);
            *(__nv_bfloat162*)&Bh[r][c + 2] = __nv_bfloat162(h2, h3);
            *(__nv_bfloat162*)&Bl[r][c]     = __nv_bfloat162(l0, l1);
            *(__nv_bfloat162*)&Bl[r][c + 2] = __nv_bfloat162(l2, l3);
        }
        __syncthreads();

        #pragma unroll
        for (int ks = 0; ks < 2; ks++) {
            const int kk = ks * 16;
            // A fragments: 2 m-tiles, hi+lo
            uint32_t ah[2][4], al[2][4];
            {
                int row = warp_m * 32 + (lane & 15);
                int col = kk + ((lane >> 4) << 3);
                #pragma unroll
                for (int mi = 0; mi < 2; mi++) {
                    ldsm_x4(ah[mi], smem_u32(&Ah[row + mi * 16][col]));
                    ldsm_x4(al[mi], smem_u32(&Al[row + mi * 16][col]));
                }
            }
            int krow = kk + (lane & 15);
            #pragma unroll
            for (int ni = 0; ni < 8; ni++) {
                int n = warp_n * 64 + ni * 8;
                uint32_t bh[2], bl[2];
                ldsm_x2t(bh, smem_u32(&Bh[krow][n]));
                ldsm_x2t(bl, smem_u32(&Bl[krow][n]));
                #pragma unroll
                for (int mi = 0; mi < 2; mi++) {
                    mma_bf16(acc[mi][ni], ah[mi], bh);
                    mma_bf16(acc[mi][ni], ah[mi], bl);
                    mma_bf16(acc[mi][ni], al[mi], bh);
                }
            }
        }
        __syncthreads();
    }

    // ---- epilogue ----
    #pragma unroll
    for (int mi = 0; mi < 2; mi++) {
        int r = m0 + warp_m * 32 + mi * 16 + (lane >> 2);
        int cb = n0 + warp_n * 64 + (lane & 3) * 2;
        #pragma unroll
        for (int ni = 0; ni < 8; ni++) {
            int c = cb + ni * 8;
            if (r < N_NODES)
                *(float2*)(g_xw + (size_t)r * HID_CH + c) =
                    make_float2(acc[mi][ni][0], acc[mi][ni][1]);
            if (r + 8 < N_NODES)
                *(float2*)(g_xw + (size_t)(r + 8) * HID_CH + c) =
                    make_float2(acc[mi][ni][2], acc[mi][ni][3]);
        }
    }
}

// ---- fused layer-1 aggregation + bias + ReLU + GEMM2 (256 -> 2) ----
__global__ __launch_bounds__(256)
void k_agg_fused(const float* __restrict__ b1, const float* __restrict__ W2) {
    __shared__ float sW2[HID_CH * OUT_CH];
    __shared__ float sb1[HID_CH];
    int tid = threadIdx.x;
    sW2[tid] = W2[tid];
    sW2[tid + 256] = W2[tid + 256];
    sb1[tid] = b1[tid];
    __syncthreads();

    int node = (blockIdx.x * blockDim.x + tid) >> 5;
    int lane = tid & 31;
    if (node >= N_NODES) return;

    float di = g_dinv[node];
    float self = di * di;
    const float4* nrow = (const float4*)(g_xw + (size_t)node * HID_CH) + lane * 2;
    float4 v0 = nrow[0], v1 = nrow[1];
    float4 acc0 = make_float4(self * v0.x, self * v0.y, self * v0.z, self * v0.w);
    float4 acc1 = make_float4(self * v1.x, self * v1.y, self * v1.z, self * v1.w);

    int begin = g_off[node];
    int end = begin + g_cnt[node];
    for (int j0 = begin; j0 < end; j0 += 32) {
        int m = end - j0; if (m > 32) m = 32;
        int   s_l = (lane < m) ? g_csr_src[j0 + lane] : 0;
        float w_l = (lane < m) ? g_csr_nrm[j0 + lane] : 0.f;
        for (int t = 0; t < m; t++) {
            int   s = __shfl_sync(0xffffffffu, s_l, t);
            float w = __shfl_sync(0xffffffffu, w_l, t);
            const float4* r = (const float4*)(g_xw + (size_t)s * HID_CH) + lane * 2;
            float4 u0 = __ldg(r);
            float4 u1 = __ldg(r + 1);
            acc0.x += w * u0.x; acc0.y += w * u0.y; acc0.z += w * u0.z; acc0.w += w * u0.w;
            acc1.x += w * u1.x; acc1.y += w * u1.y; acc1.z += w * u1.z; acc1.w += w * u1.w;
        }
    }

    int c = lane * 8;
    float h[8];
    h[0] = fmaxf(acc0.x + sb1[c + 0], 0.f);
    h[1] = fmaxf(acc0.y + sb1[c + 1], 0.f);
    h[2] = fmaxf(acc0.z + sb1[c + 2], 0.f);
    h[3] = fmaxf(acc0.w + sb1[c + 3], 0.f);
    h[4] = fmaxf(acc1.x + sb1[c + 4], 0.f);
    h[5] = fmaxf(acc1.y + sb1[c + 5], 0.f);
    h[6] = fmaxf(acc1.z + sb1[c + 6], 0.f);
    h[7] = fmaxf(acc1.w + sb1[c + 7], 0.f);
    float a0 = 0.f, a1 = 0.f;
    #pragma unroll
    for (int i = 0; i < 8; i++) {
        a0 += h[i] * sW2[(c + i) * 2];
        a1 += h[i] * sW2[(c + i) * 2 + 1];
    }
    #pragma unroll
    for (int off = 16; off > 0; off >>= 1) {
        a0 += __shfl_down_sync(0xffffffffu, a0, off);
        a1 += __shfl_down_sync(0xffffffffu, a1, off);
    }
    if (lane == 0) {
        g_hw[node * 2]     = a0;
        g_hw[node * 2 + 1] = a1;
    }
}

// ---- layer-2 aggregation via CSR ----
__global__ void k_out2(const float* __restrict__ b2, float* __restrict__ out) {
    int n = blockIdx.x * blockDim.x + threadIdx.x;
    if (n >= N_NODES) return;
    float di = g_dinv[n];
    float self = di * di;
    float a0 = g_hw[2 * n]     * self;
    float a1 = g_hw[2 * n + 1] * self;
    int begin = g_off[n];
    int end = begin + g_cnt[n];
    for (int j = begin; j < end; j++) {
        int   s = g_csr_src[j];
        float w = g_csr_nrm[j];
        a0 += w * g_hw[2 * s];
        a1 += w * g_hw[2 * s + 1];
    }
    out[2 * n]     = a0 + b2[0];
    out[2 * n + 1] = a1 + b2[1];
}

extern "C" void kernel_launch(void* const* d_in, const int* in_sizes, int n_in,
                              void* d_out, int out_size) {
    const float* x  = (const float*)d_in[0];
    const void*  ei = d_in[1];
    const float* ew = (const float*)d_in[2];
    const float* W1 = (const float*)d_in[3];
    const float* b1 = (const float*)d_in[4];
    const float* W2 = (const float*)d_in[5];
    const float* b2 = (const float*)d_in[6];
    float* out = (float*)d_out;

    const int NODE_BLKS = (N_NODES + 255) / 256;
    const int EDGE_BLKS = (N_EDGES + 255) / 256;

    k_detect<<<1, 32>>>((const unsigned long long*)ei);
    k_init<<<NODE_BLKS, 256>>>();
    k_prep<<<EDGE_BLKS, 256>>>(ei, ew);
    k_dinv<<<NODE_BLKS, 256>>>();
    k_scan1<<<N_SCAN_BLKS, SCAN_B>>>();
    k_scan2<<<1, 128>>>();
    k_scan3<<<NODE_BLKS, 256>>>();
    k_scatter<<<EDGE_BLKS, 256>>>(ew);

    dim3 g1((N_NODES + BM - 1) / BM, HID_CH / BN);
    k_gemm1_tc<<<g1, 256>>>(x, W1);

    k_agg_fused<<<(N_NODES * 32 + 255) / 256, 256>>>(b1, W2);

    k_out2<<<NODE_BLKS, 256>>>(b2, out);
}

// round 5
// speedup vs baseline: 1.8007x; 1.1166x over previous
#include <cuda_runtime.h>
#include <cuda_bf16.h>
#include <cstdint>

#define N_NODES 100000
#define N_EDGES 1600000
#define IN_CH   768
#define HID_CH  256
#define OUT_CH  2

#define SCAN_B 1024
#define N_SCAN_BLKS ((N_NODES + SCAN_B - 1) / SCAN_B)   // 98

// ---- scratch (device globals; allocation is forbidden) ----
__device__ __align__(16) float g_xw[(size_t)N_NODES * HID_CH]; // x @ W1
__device__ float g_deg [N_NODES];
__device__ float g_dinv[N_NODES];
__device__ __align__(8) float g_hw[(size_t)N_NODES * OUT_CH];  // relu(h) @ W2
__device__ int   g_src[N_EDGES];
__device__ int   g_dst[N_EDGES];
__device__ int   g_cnt[N_NODES];
__device__ int   g_off[N_NODES];
__device__ int   g_cursor[N_NODES];
__device__ int   g_bsum[N_SCAN_BLKS];
__device__ int   g_csr_src[N_EDGES];
__device__ float g_csr_nrm[N_EDGES];
__device__ int   g_is64;

// ---- detect whether edge_index is int64 or int32 (warp-parallel) ----
__global__ void k_detect(const unsigned long long* __restrict__ ei) {
    int lane = threadIdx.x;
    bool hi = false;
    for (int i = lane; i < 1024; i += 32)
        hi |= (ei[i] >> 32) != 0ull;
    unsigned m = __ballot_sync(0xffffffffu, hi);
    if (lane == 0) g_is64 = (m == 0u);
}

__global__ void k_init() {
    int i = blockIdx.x * blockDim.x + threadIdx.x;
    if (i < N_NODES) { g_deg[i] = 1.0f; g_cnt[i] = 0; }
}

__global__ void k_prep(const void* __restrict__ ei_raw, const float* __restrict__ ew) {
    int e = blockIdx.x * blockDim.x + threadIdx.x;
    if (e >= N_EDGES) return;
    int s, d;
    if (g_is64) {
        const long long* ei = (const long long*)ei_raw;
        s = (int)ei[e];
        d = (int)ei[N_EDGES + e];
    } else {
        const int* ei = (const int*)ei_raw;
        s = ei[e];
        d = ei[N_EDGES + e];
    }
    if ((unsigned)s >= N_NODES || (unsigned)d >= N_NODES) {
        g_src[e] = 0; g_dst[e] = 0;
        return;
    }
    g_src[e] = s;
    g_dst[e] = d;
    atomicAdd(&g_deg[d], ew[e]);
    atomicAdd(&g_cnt[d], 1);
}

__global__ void k_dinv() {
    int i = blockIdx.x * blockDim.x + threadIdx.x;
    if (i < N_NODES) {
        float dg = g_deg[i];
        g_dinv[i] = dg > 0.f ? rsqrtf(dg) : 0.f;
    }
}

// ---- two-level exclusive scan ----
__global__ void k_scan1() {
    __shared__ int s[SCAN_B];
    int tid = threadIdx.x;
    int i = blockIdx.x * SCAN_B + tid;
    int v = (i < N_NODES) ? g_cnt[i] : 0;
    s[tid] = v;
    __syncthreads();
    #pragma unroll
    for (int d = 1; d < SCAN_B; d <<= 1) {
        int t = (tid >= d) ? s[tid - d] : 0;
        __syncthreads();
        s[tid] += t;
        __syncthreads();
    }
    if (i < N_NODES) g_off[i] = s[tid] - v;
    if (tid == SCAN_B - 1) g_bsum[blockIdx.x] = s[tid];
}

__global__ void k_scan2() {
    __shared__ int s[128];
    int tid = threadIdx.x;
    int v = (tid < N_SCAN_BLKS) ? g_bsum[tid] : 0;
    s[tid] = v;
    __syncthreads();
    #pragma unroll
    for (int d = 1; d < 128; d <<= 1) {
        int t = (tid >= d) ? s[tid - d] : 0;
        __syncthreads();
        s[tid] += t;
        __syncthreads();
    }
    if (tid < N_SCAN_BLKS) g_bsum[tid] = s[tid] - v;
}

__global__ void k_scan3() {
    int i = blockIdx.x * blockDim.x + threadIdx.x;
    if (i < N_NODES) {
        int o = g_off[i] + g_bsum[i / SCAN_B];
        g_off[i] = o;
        g_cursor[i] = o;
    }
}

__global__ void k_scatter(const float* __restrict__ ew) {
    int e = blockIdx.x * blockDim.x + threadIdx.x;
    if (e >= N_EDGES) return;
    int s = g_src[e];
    int d = g_dst[e];
    int pos = atomicAdd(&g_cursor[d], 1);
    if ((unsigned)pos >= N_EDGES) return;
    g_csr_src[pos] = s;
    g_csr_nrm[pos] = g_dinv[s] * ew[e] * g_dinv[d];
}

// ================= tensor-core GEMM1 (bf16 split, 3-pass, reg-pipelined) =====
__device__ __forceinline__ uint32_t smem_u32(const void* p) {
    return (uint32_t)__cvta_generic_to_shared(p);
}
__device__ __forceinline__ void ldsm_x4(uint32_t* r, uint32_t addr) {
    asm volatile("ldmatrix.sync.aligned.m8n8.x4.shared.b16 {%0,%1,%2,%3}, [%4];"
        : "=r"(r[0]), "=r"(r[1]), "=r"(r[2]), "=r"(r[3]) : "r"(addr));
}
__device__ __forceinline__ void ldsm_x2t(uint32_t* r, uint32_t addr) {
    asm volatile("ldmatrix.sync.aligned.m8n8.x2.trans.shared.b16 {%0,%1}, [%2];"
        : "=r"(r[0]), "=r"(r[1]) : "r"(addr));
}
__device__ __forceinline__ void mma_bf16(float* c, const uint32_t* a, const uint32_t* b) {
    asm volatile("mma.sync.aligned.m16n8k16.row.col.f32.bf16.bf16.f32 "
        "{%0,%1,%2,%3}, {%4,%5,%6,%7}, {%8,%9}, {%0,%1,%2,%3};"
        : "+f"(c[0]), "+f"(c[1]), "+f"(c[2]), "+f"(c[3])
        : "r"(a[0]), "r"(a[1]), "r"(a[2]), "r"(a[3]), "r"(b[0]), "r"(b[1]));
}
__device__ __forceinline__ void split_bf16(float v, __nv_bfloat16& h, __nv_bfloat16& l) {
    h = __float2bfloat16(v);
    l = __float2bfloat16(v - __bfloat162float(h));
}

#define BM 128
#define BN 128
#define BK 32
#define A_PITCH 40
#define B_PITCH 136

__global__ __launch_bounds__(256, 1)
void k_gemm1_tc(const float* __restrict__ A, const float* __restrict__ B) {
    __shared__ __align__(16) __nv_bfloat16 Ah[BM][A_PITCH];
    __shared__ __align__(16) __nv_bfloat16 Al[BM][A_PITCH];
    __shared__ __align__(16) __nv_bfloat16 Bh[BK][B_PITCH];
    __shared__ __align__(16) __nv_bfloat16 Bl[BK][B_PITCH];

    const int tid  = threadIdx.x;
    const int lane = tid & 31;
    const int wid  = tid >> 5;
    const int warp_m = wid >> 1;   // 0..3, 32 rows each
    const int warp_n = wid & 1;    // 0..1, 64 cols each
    const int m0 = blockIdx.x * BM;
    const int n0 = blockIdx.y * BN;

    // per-thread fixed load coordinates
    const int ar = tid >> 1;                 // A row 0..127 (2 threads/row)
    const int ac = (tid & 1) * 16;           // A col group: 4 float4 = 16 floats
    const bool a_ok = (m0 + ar) < N_NODES;
    const int br = tid >> 3;                 // B row 0..31 (8 threads/row)
    const int bc = (tid & 7) * 16;           // B col group: 4 float4

    float4 ra[4], rb[4];
    #define LOAD_TILE(k0)                                                        \
        do {                                                                     \
            const float* ap = A + (size_t)(m0 + ar) * IN_CH + (k0) + ac;         \
            if (a_ok) {                                                          \
                ra[0] = *(const float4*)(ap);                                    \
                ra[1] = *(const float4*)(ap + 4);                                \
                ra[2] = *(const float4*)(ap + 8);                                \
                ra[3] = *(const float4*)(ap + 12);                               \
            } else {                                                             \
                ra[0] = ra[1] = ra[2] = ra[3] = make_float4(0.f, 0.f, 0.f, 0.f); \
            }                                                                    \
            const float* bp = B + (size_t)((k0) + br) * HID_CH + n0 + bc;        \
            rb[0] = *(const float4*)(bp);                                        \
            rb[1] = *(const float4*)(bp + 4);                                    \
            rb[2] = *(const float4*)(bp + 8);                                    \
            rb[3] = *(const float4*)(bp + 12);                                   \
        } while (0)

    #define STORE_TILE()                                                         \
        do {                                                                     \
            _Pragma("unroll")                                                    \
            for (int i = 0; i < 4; i++) {                                        \
                __nv_bfloat16 h0, l0, h1, l1, h2, l2, h3, l3;                    \
                split_bf16(ra[i].x, h0, l0); split_bf16(ra[i].y, h1, l1);        \
                split_bf16(ra[i].z, h2, l2); split_bf16(ra[i].w, h3, l3);        \
                int c = ac + i * 4;                                              \
                *(__nv_bfloat162*)&Ah[ar][c]     = __nv_bfloat162(h0, h1);       \
                *(__nv_bfloat162*)&Ah[ar][c + 2] = __nv_bfloat162(h2, h3);       \
                *(__nv_bfloat162*)&Al[ar][c]     = __nv_bfloat162(l0, l1);       \
                *(__nv_bfloat162*)&Al[ar][c + 2] = __nv_bfloat162(l2, l3);       \
            }                                                                    \
            _Pragma("unroll")                                                    \
            for (int i = 0; i < 4; i++) {                                        \
                __nv_bfloat16 h0, l0, h1, l1, h2, l2, h3, l3;                    \
                split_bf16(rb[i].x, h0, l0); split_bf16(rb[i].y, h1, l1);        \
                split_bf16(rb[i].z, h2, l2); split_bf16(rb[i].w, h3, l3);        \
                int c = bc + i * 4;                                              \
                *(__nv_bfloat162*)&Bh[br][c]     = __nv_bfloat162(h0, h1);       \
                *(__nv_bfloat162*)&Bh[br][c + 2] = __nv_bfloat162(h2, h3);       \
                *(__nv_bfloat162*)&Bl[br][c]     = __nv_bfloat162(l0, l1);       \
                *(__nv_bfloat162*)&Bl[br][c + 2] = __nv_bfloat162(l2, l3);       \
            }                                                                    \
        } while (0)

    float acc[2][8][4];
    #pragma unroll
    for (int mi = 0; mi < 2; mi++)
        #pragma unroll
        for (int ni = 0; ni < 8; ni++)
            #pragma unroll
            for (int q = 0; q < 4; q++) acc[mi][ni][q] = 0.f;

    LOAD_TILE(0);

    for (int k0 = 0; k0 < IN_CH; k0 += BK) {
        STORE_TILE();
        __syncthreads();
        if (k0 + BK < IN_CH) LOAD_TILE(k0 + BK);   // prefetch next tile (regs)

        #pragma unroll
        for (int ks = 0; ks < 2; ks++) {
            const int kk = ks * 16;
            uint32_t ah[2][4], al[2][4];
            {
                int row = warp_m * 32 + (lane & 15);
                int col = kk + ((lane >> 4) << 3);
                #pragma unroll
                for (int mi = 0; mi < 2; mi++) {
                    ldsm_x4(ah[mi], smem_u32(&Ah[row + mi * 16][col]));
                    ldsm_x4(al[mi], smem_u32(&Al[row + mi * 16][col]));
                }
            }
            int krow = kk + (lane & 15);
            #pragma unroll
            for (int ni = 0; ni < 8; ni++) {
                int n = warp_n * 64 + ni * 8;
                uint32_t bh[2], bl[2];
                ldsm_x2t(bh, smem_u32(&Bh[krow][n]));
                ldsm_x2t(bl, smem_u32(&Bl[krow][n]));
                #pragma unroll
                for (int mi = 0; mi < 2; mi++) {
                    mma_bf16(acc[mi][ni], ah[mi], bh);
                    mma_bf16(acc[mi][ni], ah[mi], bl);
                    mma_bf16(acc[mi][ni], al[mi], bh);
                }
            }
        }
        __syncthreads();
    }

    // ---- epilogue ----
    #pragma unroll
    for (int mi = 0; mi < 2; mi++) {
        int r = m0 + warp_m * 32 + mi * 16 + (lane >> 2);
        int cb = n0 + warp_n * 64 + (lane & 3) * 2;
        #pragma unroll
        for (int ni = 0; ni < 8; ni++) {
            int c = cb + ni * 8;
            if (r < N_NODES)
                *(float2*)(g_xw + (size_t)r * HID_CH + c) =
                    make_float2(acc[mi][ni][0], acc[mi][ni][1]);
            if (r + 8 < N_NODES)
                *(float2*)(g_xw + (size_t)(r + 8) * HID_CH + c) =
                    make_float2(acc[mi][ni][2], acc[mi][ni][3]);
        }
    }
}

// ---- fused layer-1 aggregation + bias + ReLU + GEMM2 (256 -> 2) ----
__global__ __launch_bounds__(256)
void k_agg_fused(const float* __restrict__ b1, const float* __restrict__ W2) {
    __shared__ float sW2[HID_CH * OUT_CH];
    __shared__ float sb1[HID_CH];
    int tid = threadIdx.x;
    sW2[tid] = W2[tid];
    sW2[tid + 256] = W2[tid + 256];
    sb1[tid] = b1[tid];
    __syncthreads();

    int node = (blockIdx.x * blockDim.x + tid) >> 5;
    int lane = tid & 31;
    if (node >= N_NODES) return;

    float di = g_dinv[node];
    float self = di * di;
    const float4* nrow = (const float4*)(g_xw + (size_t)node * HID_CH) + lane * 2;
    float4 v0 = nrow[0], v1 = nrow[1];
    float4 acc0 = make_float4(self * v0.x, self * v0.y, self * v0.z, self * v0.w);
    float4 acc1 = make_float4(self * v1.x, self * v1.y, self * v1.z, self * v1.w);

    int begin = g_off[node];
    int end = begin + g_cnt[node];
    for (int j0 = begin; j0 < end; j0 += 32) {
        int m = end - j0; if (m > 32) m = 32;
        int   s_l = (lane < m) ? g_csr_src[j0 + lane] : 0;
        float w_l = (lane < m) ? g_csr_nrm[j0 + lane] : 0.f;
        for (int t = 0; t < m; t++) {
            int   s = __shfl_sync(0xffffffffu, s_l, t);
            float w = __shfl_sync(0xffffffffu, w_l, t);
            const float4* r = (const float4*)(g_xw + (size_t)s * HID_CH) + lane * 2;
            float4 u0 = __ldg(r);
            float4 u1 = __ldg(r + 1);
            acc0.x += w * u0.x; acc0.y += w * u0.y; acc0.z += w * u0.z; acc0.w += w * u0.w;
            acc1.x += w * u1.x; acc1.y += w * u1.y; acc1.z += w * u1.z; acc1.w += w * u1.w;
        }
    }

    int c = lane * 8;
    float h[8];
    h[0] = fmaxf(acc0.x + sb1[c + 0], 0.f);
    h[1] = fmaxf(acc0.y + sb1[c + 1], 0.f);
    h[2] = fmaxf(acc0.z + sb1[c + 2], 0.f);
    h[3] = fmaxf(acc0.w + sb1[c + 3], 0.f);
    h[4] = fmaxf(acc1.x + sb1[c + 4], 0.f);
    h[5] = fmaxf(acc1.y + sb1[c + 5], 0.f);
    h[6] = fmaxf(acc1.z + sb1[c + 6], 0.f);
    h[7] = fmaxf(acc1.w + sb1[c + 7], 0.f);
    float a0 = 0.f, a1 = 0.f;
    #pragma unroll
    for (int i = 0; i < 8; i++) {
        a0 += h[i] * sW2[(c + i) * 2];
        a1 += h[i] * sW2[(c + i) * 2 + 1];
    }
    #pragma unroll
    for (int off = 16; off > 0; off >>= 1) {
        a0 += __shfl_down_sync(0xffffffffu, a0, off);
        a1 += __shfl_down_sync(0xffffffffu, a1, off);
    }
    if (lane == 0) {
        g_hw[node * 2]     = a0;
        g_hw[node * 2 + 1] = a1;
    }
}

// ---- layer-2 aggregation via CSR ----
__global__ void k_out2(const float* __restrict__ b2, float* __restrict__ out) {
    int n = blockIdx.x * blockDim.x + threadIdx.x;
    if (n >= N_NODES) return;
    float di = g_dinv[n];
    float self = di * di;
    float a0 = g_hw[2 * n]     * self;
    float a1 = g_hw[2 * n + 1] * self;
    int begin = g_off[n];
    int end = begin + g_cnt[n];
    for (int j = begin; j < end; j++) {
        int   s = g_csr_src[j];
        float w = g_csr_nrm[j];
        a0 += w * g_hw[2 * s];
        a1 += w * g_hw[2 * s + 1];
    }
    out[2 * n]     = a0 + b2[0];
    out[2 * n + 1] = a1 + b2[1];
}

extern "C" void kernel_launch(void* const* d_in, const int* in_sizes, int n_in,
                              void* d_out, int out_size) {
    const float* x  = (const float*)d_in[0];
    const void*  ei = d_in[1];
    const float* ew = (const float*)d_in[2];
    const float* W1 = (const float*)d_in[3];
    const float* b1 = (const float*)d_in[4];
    const float* W2 = (const float*)d_in[5];
    const float* b2 = (const float*)d_in[6];
    float* out = (float*)d_out;

    const int NODE_BLKS = (N_NODES + 255) / 256;
    const int EDGE_BLKS = (N_EDGES + 255) / 256;

    k_detect<<<1, 32>>>((const unsigned long long*)ei);
    k_init<<<NODE_BLKS, 256>>>();
    k_prep<<<EDGE_BLKS, 256>>>(ei, ew);
    k_dinv<<<NODE_BLKS, 256>>>();
    k_scan1<<<N_SCAN_BLKS, SCAN_B>>>();
    k_scan2<<<1, 128>>>();
    k_scan3<<<NODE_BLKS, 256>>>();
    k_scatter<<<EDGE_BLKS, 256>>>(ew);

    dim3 g1((N_NODES + BM - 1) / BM, HID_CH / BN);
    k_gemm1_tc<<<g1, 256>>>(x, W1);

    k_agg_fused<<<(N_NODES * 32 + 255) / 256, 256>>>(b1, W2);

    k_out2<<<NODE_BLKS, 256>>>(b2, out);
}

// round 6
// speedup vs baseline: 1.8169x; 1.0090x over previous
#include <cuda_runtime.h>
#include <cuda_bf16.h>
#include <cstdint>

#define N_NODES 100000
#define N_EDGES 1600000
#define IN_CH   768
#define HID_CH  256
#define OUT_CH  2

#define SCAN_B 1024
#define N_SCAN_BLKS ((N_NODES + SCAN_B - 1) / SCAN_B)   // 98

// ---- scratch (device globals; allocation is forbidden) ----
__device__ __align__(16) float g_xw[(size_t)N_NODES * HID_CH]; // x @ W1
__device__ float g_deg [N_NODES];
__device__ float g_dinv[N_NODES];
__device__ __align__(8) float g_hw[(size_t)N_NODES * OUT_CH];  // relu(h) @ W2
__device__ int   g_cnt[N_NODES];
__device__ int   g_off[N_NODES];
__device__ int   g_cursor[N_NODES];
__device__ int   g_bsum[N_SCAN_BLKS];
__device__ int   g_csr_src[N_EDGES];
__device__ float g_csr_nrm[N_EDGES];
__device__ int   g_is64;

// ---- detect whether edge_index is int64 or int32 (warp-parallel) ----
__global__ void k_detect(const unsigned long long* __restrict__ ei) {
    int lane = threadIdx.x;
    bool hi = false;
    for (int i = lane; i < 1024; i += 32)
        hi |= (ei[i] >> 32) != 0ull;
    unsigned m = __ballot_sync(0xffffffffu, hi);
    if (lane == 0) g_is64 = (m == 0u);
}

__global__ void k_init() {
    int i = blockIdx.x * blockDim.x + threadIdx.x;
    if (i < N_NODES) { g_deg[i] = 1.0f; g_cnt[i] = 0; }
}

__device__ __forceinline__ void load_edge(const void* ei_raw, int e, int& s, int& d) {
    if (g_is64) {
        const long long* ei = (const long long*)ei_raw;
        s = (int)ei[e];
        d = (int)ei[N_EDGES + e];
    } else {
        const int* ei = (const int*)ei_raw;
        s = ei[e];
        d = ei[N_EDGES + e];
    }
    if ((unsigned)s >= N_NODES) s = 0;
    if ((unsigned)d >= N_NODES) d = 0;
}

__global__ void k_prep(const void* __restrict__ ei_raw, const float* __restrict__ ew) {
    int e = blockIdx.x * blockDim.x + threadIdx.x;
    if (e >= N_EDGES) return;
    int s, d;
    load_edge(ei_raw, e, s, d);
    atomicAdd(&g_deg[d], ew[e]);
    atomicAdd(&g_cnt[d], 1);
}

__global__ void k_dinv() {
    int i = blockIdx.x * blockDim.x + threadIdx.x;
    if (i < N_NODES) {
        float dg = g_deg[i];
        g_dinv[i] = dg > 0.f ? rsqrtf(dg) : 0.f;
    }
}

// ---- two-level exclusive scan ----
__global__ void k_scan1() {
    __shared__ int s[SCAN_B];
    int tid = threadIdx.x;
    int i = blockIdx.x * SCAN_B + tid;
    int v = (i < N_NODES) ? g_cnt[i] : 0;
    s[tid] = v;
    __syncthreads();
    #pragma unroll
    for (int d = 1; d < SCAN_B; d <<= 1) {
        int t = (tid >= d) ? s[tid - d] : 0;
        __syncthreads();
        s[tid] += t;
        __syncthreads();
    }
    if (i < N_NODES) g_off[i] = s[tid] - v;
    if (tid == SCAN_B - 1) g_bsum[blockIdx.x] = s[tid];
}

__global__ void k_scan2() {
    __shared__ int s[128];
    int tid = threadIdx.x;
    int v = (tid < N_SCAN_BLKS) ? g_bsum[tid] : 0;
    s[tid] = v;
    __syncthreads();
    #pragma unroll
    for (int d = 1; d < 128; d <<= 1) {
        int t = (tid >= d) ? s[tid - d] : 0;
        __syncthreads();
        s[tid] += t;
        __syncthreads();
    }
    if (tid < N_SCAN_BLKS) g_bsum[tid] = s[tid] - v;
}

__global__ void k_scan3() {
    int i = blockIdx.x * blockDim.x + threadIdx.x;
    if (i < N_NODES) {
        int o = g_off[i] + g_bsum[i / SCAN_B];
        g_off[i] = o;
        g_cursor[i] = o;
    }
}

__global__ void k_scatter(const void* __restrict__ ei_raw, const float* __restrict__ ew) {
    int e = blockIdx.x * blockDim.x + threadIdx.x;
    if (e >= N_EDGES) return;
    int s, d;
    load_edge(ei_raw, e, s, d);
    int pos = atomicAdd(&g_cursor[d], 1);
    if ((unsigned)pos >= N_EDGES) return;
    g_csr_src[pos] = s;
    g_csr_nrm[pos] = g_dinv[s] * ew[e] * g_dinv[d];
}

// ====== tensor-core GEMM1 (bf16 split, 3-pass, reg + smem double-buffer) ====
__device__ __forceinline__ uint32_t smem_u32(const void* p) {
    return (uint32_t)__cvta_generic_to_shared(p);
}
__device__ __forceinline__ void ldsm_x4(uint32_t* r, uint32_t addr) {
    asm volatile("ldmatrix.sync.aligned.m8n8.x4.shared.b16 {%0,%1,%2,%3}, [%4];"
        : "=r"(r[0]), "=r"(r[1]), "=r"(r[2]), "=r"(r[3]) : "r"(addr));
}
__device__ __forceinline__ void ldsm_x2t(uint32_t* r, uint32_t addr) {
    asm volatile("ldmatrix.sync.aligned.m8n8.x2.trans.shared.b16 {%0,%1}, [%2];"
        : "=r"(r[0]), "=r"(r[1]) : "r"(addr));
}
__device__ __forceinline__ void mma_bf16(float* c, const uint32_t* a, const uint32_t* b) {
    asm volatile("mma.sync.aligned.m16n8k16.row.col.f32.bf16.bf16.f32 "
        "{%0,%1,%2,%3}, {%4,%5,%6,%7}, {%8,%9}, {%0,%1,%2,%3};"
        : "+f"(c[0]), "+f"(c[1]), "+f"(c[2]), "+f"(c[3])
        : "r"(a[0]), "r"(a[1]), "r"(a[2]), "r"(a[3]), "r"(b[0]), "r"(b[1]));
}
__device__ __forceinline__ void split_bf16(float v, __nv_bfloat16& h, __nv_bfloat16& l) {
    h = __float2bfloat16(v);
    l = __float2bfloat16(v - __bfloat162float(h));
}

#define BM 128
#define BN 128
#define BK 32
#define A_PITCH 40
#define B_PITCH 136
#define A_STAGE (BM * A_PITCH)      // halves per stage
#define B_STAGE (BK * B_PITCH)
#define GEMM_SMEM_BYTES ((4 * A_STAGE + 4 * B_STAGE) * 2)   // 75776

__global__ __launch_bounds__(256, 1)
void k_gemm1_tc(const float* __restrict__ A, const float* __restrict__ B) {
    extern __shared__ __align__(16) __nv_bfloat16 sm[];
    __nv_bfloat16* AH = sm;                     // [2][BM][A_PITCH]
    __nv_bfloat16* AL = AH + 2 * A_STAGE;
    __nv_bfloat16* BH = AL + 2 * A_STAGE;       // [2][BK][B_PITCH]
    __nv_bfloat16* BL = BH + 2 * B_STAGE;

    const int tid  = threadIdx.x;
    const int lane = tid & 31;
    const int wid  = tid >> 5;
    const int warp_m = wid >> 1;
    const int warp_n = wid & 1;
    const int m0 = blockIdx.x * BM;
    const int n0 = blockIdx.y * BN;

    const int ar = tid >> 1;
    const int ac = (tid & 1) * 16;
    const bool a_ok = (m0 + ar) < N_NODES;
    const int br = tid >> 3;
    const int bc = (tid & 7) * 16;

    float4 ra[4], rb[4];
    #define LOAD_TILE(k0)                                                        \
        do {                                                                     \
            const float* ap = A + (size_t)(m0 + ar) * IN_CH + (k0) + ac;         \
            if (a_ok) {                                                          \
                ra[0] = *(const float4*)(ap);                                    \
                ra[1] = *(const float4*)(ap + 4);                                \
                ra[2] = *(const float4*)(ap + 8);                                \
                ra[3] = *(const float4*)(ap + 12);                               \
            } else {                                                             \
                ra[0] = ra[1] = ra[2] = ra[3] = make_float4(0.f, 0.f, 0.f, 0.f); \
            }                                                                    \
            const float* bp = B + (size_t)((k0) + br) * HID_CH + n0 + bc;        \
            rb[0] = *(const float4*)(bp);                                        \
            rb[1] = *(const float4*)(bp + 4);                                    \
            rb[2] = *(const float4*)(bp + 8);                                    \
            rb[3] = *(const float4*)(bp + 12);                                   \
        } while (0)

    #define STORE_TILE(st)                                                       \
        do {                                                                     \
            __nv_bfloat16* ah = AH + (st) * A_STAGE + ar * A_PITCH + ac;         \
            __nv_bfloat16* al = AL + (st) * A_STAGE + ar * A_PITCH + ac;         \
            __nv_bfloat16* bh = BH + (st) * B_STAGE + br * B_PITCH + bc;         \
            __nv_bfloat16* bl = BL + (st) * B_STAGE + br * B_PITCH + bc;         \
            _Pragma("unroll")                                                    \
            for (int i = 0; i < 4; i++) {                                        \
                __nv_bfloat16 h0, l0, h1, l1, h2, l2, h3, l3;                    \
                split_bf16(ra[i].x, h0, l0); split_bf16(ra[i].y, h1, l1);        \
                split_bf16(ra[i].z, h2, l2); split_bf16(ra[i].w, h3, l3);        \
                *(__nv_bfloat162*)(ah + i * 4)     = __nv_bfloat162(h0, h1);     \
                *(__nv_bfloat162*)(ah + i * 4 + 2) = __nv_bfloat162(h2, h3);     \
                *(__nv_bfloat162*)(al + i * 4)     = __nv_bfloat162(l0, l1);     \
                *(__nv_bfloat162*)(al + i * 4 + 2) = __nv_bfloat162(l2, l3);     \
            }                                                                    \
            _Pragma("unroll")                                                    \
            for (int i = 0; i < 4; i++) {                                        \
                __nv_bfloat16 h0, l0, h1, l1, h2, l2, h3, l3;                    \
                split_bf16(rb[i].x, h0, l0); split_bf16(rb[i].y, h1, l1);        \
                split_bf16(rb[i].z, h2, l2); split_bf16(rb[i].w, h3, l3);        \
                *(__nv_bfloat162*)(bh + i * 4)     = __nv_bfloat162(h0, h1);     \
                *(__nv_bfloat162*)(bh + i * 4 + 2) = __nv_bfloat162(h2, h3);     \
                *(__nv_bfloat162*)(bl + i * 4)     = __nv_bfloat162(l0, l1);     \
                *(__nv_bfloat162*)(bl + i * 4 + 2) = __nv_bfloat162(l2, l3);     \
            }                                                                    \
        } while (0)

    float acc[2][8][4];
    #pragma unroll
    for (int mi = 0; mi < 2; mi++)
        #pragma unroll
        for (int ni = 0; ni < 8; ni++)
            #pragma unroll
            for (int q = 0; q < 4; q++) acc[mi][ni][q] = 0.f;

    LOAD_TILE(0);
    STORE_TILE(0);
    __syncthreads();

    int stage = 0;
    for (int k0 = 0; k0 < IN_CH; k0 += BK) {
        const bool has_next = (k0 + BK) < IN_CH;
        if (has_next) LOAD_TILE(k0 + BK);      // LDG in flight during MMAs

        const __nv_bfloat16* AHs = AH + stage * A_STAGE;
        const __nv_bfloat16* ALs = AL + stage * A_STAGE;
        const __nv_bfloat16* BHs = BH + stage * B_STAGE;
        const __nv_bfloat16* BLs = BL + stage * B_STAGE;
        #pragma unroll
        for (int ks = 0; ks < 2; ks++) {
            const int kk = ks * 16;
            uint32_t ah[2][4], al[2][4];
            {
                int row = warp_m * 32 + (lane & 15);
                int col = kk + ((lane >> 4) << 3);
                #pragma unroll
                for (int mi = 0; mi < 2; mi++) {
                    ldsm_x4(ah[mi], smem_u32(AHs + (row + mi * 16) * A_PITCH + col));
                    ldsm_x4(al[mi], smem_u32(ALs + (row + mi * 16) * A_PITCH + col));
                }
            }
            int krow = kk + (lane & 15);
            #pragma unroll
            for (int ni = 0; ni < 8; ni++) {
                int n = warp_n * 64 + ni * 8;
                uint32_t bh[2], bl[2];
                ldsm_x2t(bh, smem_u32(BHs + krow * B_PITCH + n));
                ldsm_x2t(bl, smem_u32(BLs + krow * B_PITCH + n));
                #pragma unroll
                for (int mi = 0; mi < 2; mi++) {
                    mma_bf16(acc[mi][ni], ah[mi], bh);
                    mma_bf16(acc[mi][ni], ah[mi], bl);
                    mma_bf16(acc[mi][ni], al[mi], bh);
                }
            }
        }
        if (has_next) STORE_TILE(stage ^ 1);   // fill other stage, overlaps MMA
        __syncthreads();
        stage ^= 1;
    }

    #pragma unroll
    for (int mi = 0; mi < 2; mi++) {
        int r = m0 + warp_m * 32 + mi * 16 + (lane >> 2);
        int cb = n0 + warp_n * 64 + (lane & 3) * 2;
        #pragma unroll
        for (int ni = 0; ni < 8; ni++) {
            int c = cb + ni * 8;
            if (r < N_NODES)
                *(float2*)(g_xw + (size_t)r * HID_CH + c) =
                    make_float2(acc[mi][ni][0], acc[mi][ni][1]);
            if (r + 8 < N_NODES)
                *(float2*)(g_xw + (size_t)(r + 8) * HID_CH + c) =
                    make_float2(acc[mi][ni][2], acc[mi][ni][3]);
        }
    }
}

// ---- fused layer-1 aggregation + bias + ReLU + GEMM2 (256 -> 2) ----
__global__ __launch_bounds__(256)
void k_agg_fused(const float* __restrict__ b1, const float* __restrict__ W2) {
    __shared__ float sW2[HID_CH * OUT_CH];
    __shared__ float sb1[HID_CH];
    int tid = threadIdx.x;
    sW2[tid] = W2[tid];
    sW2[tid + 256] = W2[tid + 256];
    sb1[tid] = b1[tid];
    __syncthreads();

    int node = (blockIdx.x * blockDim.x + tid) >> 5;
    int lane = tid & 31;
    if (node >= N_NODES) return;

    float di = g_dinv[node];
    float self = di * di;
    const float4* nrow = (const float4*)(g_xw + (size_t)node * HID_CH) + lane * 2;
    float4 v0 = nrow[0], v1 = nrow[1];
    float4 acc0 = make_float4(self * v0.x, self * v0.y, self * v0.z, self * v0.w);
    float4 acc1 = make_float4(self * v1.x, self * v1.y, self * v1.z, self * v1.w);

    int begin = g_off[node];
    int end = begin + g_cnt[node];
    for (int j0 = begin; j0 < end; j0 += 32) {
        int m = end - j0; if (m > 32) m = 32;
        int   s_l = (lane < m) ? g_csr_src[j0 + lane] : 0;
        float w_l = (lane < m) ? g_csr_nrm[j0 + lane] : 0.f;
        for (int t = 0; t < m; t++) {
            int   s = __shfl_sync(0xffffffffu, s_l, t);
            float w = __shfl_sync(0xffffffffu, w_l, t);
            const float4* r = (const float4*)(g_xw + (size_t)s * HID_CH) + lane * 2;
            float4 u0 = __ldg(r);
            float4 u1 = __ldg(r + 1);
            acc0.x += w * u0.x; acc0.y += w * u0.y; acc0.z += w * u0.z; acc0.w += w * u0.w;
            acc1.x += w * u1.x; acc1.y += w * u1.y; acc1.z += w * u1.z; acc1.w += w * u1.w;
        }
    }

    int c = lane * 8;
    float h[8];
    h[0] = fmaxf(acc0.x + sb1[c + 0], 0.f);
    h[1] = fmaxf(acc0.y + sb1[c + 1], 0.f);
    h[2] = fmaxf(acc0.z + sb1[c + 2], 0.f);
    h[3] = fmaxf(acc0.w + sb1[c + 3], 0.f);
    h[4] = fmaxf(acc1.x + sb1[c + 4], 0.f);
    h[5] = fmaxf(acc1.y + sb1[c + 5], 0.f);
    h[6] = fmaxf(acc1.z + sb1[c + 6], 0.f);
    h[7] = fmaxf(acc1.w + sb1[c + 7], 0.f);
    float a0 = 0.f, a1 = 0.f;
    #pragma unroll
    for (int i = 0; i < 8; i++) {
        a0 += h[i] * sW2[(c + i) * 2];
        a1 += h[i] * sW2[(c + i) * 2 + 1];
    }
    #pragma unroll
    for (int off = 16; off > 0; off >>= 1) {
        a0 += __shfl_down_sync(0xffffffffu, a0, off);
        a1 += __shfl_down_sync(0xffffffffu, a1, off);
    }
    if (lane == 0) {
        g_hw[node * 2]     = a0;
        g_hw[node * 2 + 1] = a1;
    }
}

// ---- layer-2 aggregation via CSR ----
__global__ void k_out2(const float* __restrict__ b2, float* __restrict__ out) {
    int n = blockIdx.x * blockDim.x + threadIdx.x;
    if (n >= N_NODES) return;
    float di = g_dinv[n];
    float self = di * di;
    float a0 = g_hw[2 * n]     * self;
    float a1 = g_hw[2 * n + 1] * self;
    int begin = g_off[n];
    int end = begin + g_cnt[n];
    for (int j = begin; j < end; j++) {
        int   s = g_csr_src[j];
        float w = g_csr_nrm[j];
        a0 += w * g_hw[2 * s];
        a1 += w * g_hw[2 * s + 1];
    }
    out[2 * n]     = a0 + b2[0];
    out[2 * n + 1] = a1 + b2[1];
}

extern "C" void kernel_launch(void* const* d_in, const int* in_sizes, int n_in,
                              void* d_out, int out_size) {
    const float* x  = (const float*)d_in[0];
    const void*  ei = d_in[1];
    const float* ew = (const float*)d_in[2];
    const float* W1 = (const float*)d_in[3];
    const float* b1 = (const float*)d_in[4];
    const float* W2 = (const float*)d_in[5];
    const float* b2 = (const float*)d_in[6];
    float* out = (float*)d_out;

    const int NODE_BLKS = (N_NODES + 255) / 256;
    const int EDGE_BLKS = (N_EDGES + 255) / 256;

    cudaFuncSetAttribute(k_gemm1_tc,
                         cudaFuncAttributeMaxDynamicSharedMemorySize, GEMM_SMEM_BYTES);

    // Launch order puts GEMM 4th so the fixed ncu window profiles it.
    k_detect<<<1, 32>>>((const unsigned long long*)ei);
    k_init<<<NODE_BLKS, 256>>>();
    k_prep<<<EDGE_BLKS, 256>>>(ei, ew);

    dim3 g1((N_NODES + BM - 1) / BM, HID_CH / BN);
    k_gemm1_tc<<<g1, 256, GEMM_SMEM_BYTES>>>(x, W1);

    k_dinv<<<NODE_BLKS, 256>>>();
    k_scan1<<<N_SCAN_BLKS, SCAN_B>>>();
    k_scan2<<<1, 128>>>();
    k_scan3<<<NODE_BLKS, 256>>>();
    k_scatter<<<EDGE_BLKS, 256>>>(ei, ew);

    k_agg_fused<<<(N_NODES * 32 + 255) / 256, 256>>>(b1, W2);

    k_out2<<<NODE_BLKS, 256>>>(b2, out);
}